// round 1
// baseline (speedup 1.0000x reference)
#include <cuda_runtime.h>

// SAG: CSR SpMM neighbor aggregation.
//   out[i][d] = sum_{e in [rp[i], rp[i+1])} X[col[e]][d],  D = 48, deg = 16 (fixed)
//
// Strategy: 16 threads per destination node. Lane l owns features {l, l+16, l+32}
// so each gathered 192B row is read as 3 fully-coalesced 64B transactions.
// X (19.2 MB) fits in L2, so the 307 MB of gather traffic is L2-resident:
// kernel is LTS-throughput bound. Fully unrolled edge loop exposes ~48
// independent loads per group to hide L2 latency.

#define D_FEAT 48
#define LANES_PER_NODE 16

__global__ __launch_bounds__(256, 8)
void sag_kernel(const float* __restrict__ X,
                const int* __restrict__ row_pointers,
                const int* __restrict__ column_index,
                float* __restrict__ out,
                int n_nodes)
{
    const int tid   = blockIdx.x * blockDim.x + threadIdx.x;
    const int node  = tid / LANES_PER_NODE;
    const int lane  = tid & (LANES_PER_NODE - 1);   // 0..15 within group

    if (node >= n_nodes) return;

    const int base = row_pointers[node];
    const int deg  = row_pointers[node + 1] - base;

    // Each of the 16 lanes loads one edge index for this node (coalesced),
    // then broadcasts per-edge via shfl within the 16-lane segment.
    int my_idx = 0;
    if (lane < deg) my_idx = column_index[base + lane];

    float a0 = 0.f, a1 = 0.f, a2 = 0.f;

    if (deg == LANES_PER_NODE) {
        // Fast path (always taken for this dataset): fully unrolled, max MLP.
        #pragma unroll
        for (int e = 0; e < LANES_PER_NODE; ++e) {
            const int idx = __shfl_sync(0xffffffffu, my_idx, e, LANES_PER_NODE);
            const float* __restrict__ row = X + (long long)idx * D_FEAT;
            a0 += __ldg(row + lane);
            a1 += __ldg(row + lane + 16);
            a2 += __ldg(row + lane + 32);
        }
    } else {
        // Generic fallback (robustness only; deg is 16 by construction).
        for (int e = 0; e < deg; ++e) {
            int idx;
            if (e < LANES_PER_NODE) {
                idx = __shfl_sync(0xffffffffu, my_idx, e, LANES_PER_NODE);
            } else {
                idx = column_index[base + e];
            }
            const float* __restrict__ row = X + (long long)idx * D_FEAT;
            a0 += __ldg(row + lane);
            a1 += __ldg(row + lane + 16);
            a2 += __ldg(row + lane + 32);
        }
    }

    float* __restrict__ orow = out + (long long)node * D_FEAT;
    orow[lane]      = a0;
    orow[lane + 16] = a1;
    orow[lane + 32] = a2;
}

extern "C" void kernel_launch(void* const* d_in, const int* in_sizes, int n_in,
                              void* d_out, int out_size)
{
    const float* X   = (const float*)d_in[0];
    const int*   rp  = (const int*)d_in[1];
    const int*   col = (const int*)d_in[2];
    float*       out = (float*)d_out;

    const int n_nodes = in_sizes[1] - 1;  // row_pointers has n+1 entries

    const int threads = 256;
    const int nodes_per_block = threads / LANES_PER_NODE;  // 16
    const int blocks = (n_nodes + nodes_per_block - 1) / nodes_per_block;

    sag_kernel<<<blocks, threads>>>(X, rp, col, out, n_nodes);
}